// round 2
// baseline (speedup 1.0000x reference)
#include <cuda_runtime.h>
#include <cstdint>

#define B_  32
#define T_  512
#define H_  512
#define V_  4096
#define M_  (B_ * T_)                     /* 16384 rows of output */
#define YELEMS ((long long)M_ * V_)       /* 67108864 */

// Hidden states for all timesteps: [t][b][k], fp32. 32 MB device scratch.
__device__ float g_Hs[M_ * H_];

// ---------------- f32x2 helpers ----------------
__device__ __forceinline__ void fma2(uint64_t& d, uint64_t a, uint64_t b) {
    asm("fma.rn.f32x2 %0, %1, %2, %0;" : "+l"(d) : "l"(a), "l"(b));
}
__device__ __forceinline__ uint64_t dup2(float x) {
    uint64_t r; asm("mov.b64 %0, {%1, %1};" : "=l"(r) : "f"(x)); return r;
}
__device__ __forceinline__ float2 unpk(uint64_t v) {
    float2 f; asm("mov.b64 {%0, %1}, %2;" : "=f"(f.x), "=f"(f.y) : "l"(v)); return f;
}

// =====================================================================
// Kernel 1: recurrence. Grid = 128 CTAs = 16 batch-groups x 8 cluster
// CTAs. Each CTA: 2 batch rows x 64 hidden columns. W_hh column slice
// in registers. Per-step sync: one cluster barrier (8 CTAs per
// batch-group; batch-groups are fully independent).
// Thread layout: 16 warps; warp w owns k-chunk [w*32, w*32+32);
// lane l owns column pair (j0 + 2l, j0 + 2l + 1).
// =====================================================================
__global__ void __launch_bounds__(512, 1) __cluster_dims__(8, 1, 1)
k_rnn(const int* __restrict__ X, const float* __restrict__ state,
      const float* __restrict__ W_xh, const float* __restrict__ W_hh,
      const float* __restrict__ b_h)
{
    __shared__ double2 hsmD[512];   // hsmD[k] = packed (h_b0,h_b0 | h_b1,h_b1)
    __shared__ float4  part[512];   // per-thread partial sums

    const int tid = threadIdx.x;
    const int w   = tid >> 5;
    const int l   = tid & 31;
    const int bg  = blockIdx.x >> 3;   // 0..15 batch group
    const int cr  = blockIdx.x & 7;    // 0..7  cluster rank (column group)
    const int b0  = bg * 2;
    const int j0  = cr * 64;
    const int jj  = j0 + l * 2;        // this thread's column pair
    const int k0  = w * 32;

    // W_hh[k][jj..jj+1] for k in [k0, k0+32): 32 packed pairs in registers.
    uint64_t wr[32];
#pragma unroll
    for (int kk = 0; kk < 32; kk++)
        wr[kk] = *(const uint64_t*)(W_hh + (size_t)(k0 + kk) * H_ + jj);

    for (int t = 0; t < T_; t++) {
        const float* s0 = (t == 0)
            ? (state + (size_t)b0 * H_)
            : (g_Hs + ((size_t)(t - 1) * B_ + b0) * H_);
        {   // fill hsm: hsmD[k] = (h0[k], h0[k], h1[k], h1[k])
            float a = s0[tid];
            float b = s0[H_ + tid];
            ((float4*)hsmD)[tid] = make_float4(a, a, b, b);
        }
        __syncthreads();

        uint64_t acc0 = 0, acc1 = 0;   // (0.0f, 0.0f) packed
#pragma unroll
        for (int kk = 0; kk < 32; kk++) {
            double2 hd = hsmD[k0 + kk];                 // one LDS.128 broadcast
            fma2(acc0, __double_as_longlong(hd.x), wr[kk]);
            fma2(acc1, __double_as_longlong(hd.y), wr[kk]);
        }
        float2 a0 = unpk(acc0), a1 = unpk(acc1);
        part[w * 32 + l] = make_float4(a0.x, a0.y, a1.x, a1.y);
        __syncthreads();

        if (tid < 128) {
            int b  = tid >> 6;          // 0..1
            int jl = tid & 63;          // local column
            const float* pf = (const float*)part;
            int off = (jl >> 1) * 4 + b * 2 + (jl & 1);
            float s = 0.f;
#pragma unroll
            for (int ww = 0; ww < 16; ww++) s += pf[ww * 128 + off];
            int br  = b0 + b;
            int jgl = j0 + jl;
            int tok = X[br * T_ + t];
            float v = s + b_h[jgl] + W_xh[(size_t)tok * H_ + jgl];
            g_Hs[((size_t)t * B_ + br) * H_ + jgl] = tanhf(v);
        }
        // release + L1 flush + acquire across the 8 CTAs of this batch group
        asm volatile("barrier.cluster.arrive.aligned;" ::: "memory");
        asm volatile("barrier.cluster.wait.aligned;" ::: "memory");
    }
}

// =====================================================================
// Kernel 2: Y = Hs @ W_hq + b_q   (16384x512)@(512x4096), fp32.
// 128x128 tiles, 256 threads, 8x8 microtile, f32x2 FMA, double buffer.
// =====================================================================
__global__ void __launch_bounds__(256)
k_gemm(const float* __restrict__ Bmat, const float* __restrict__ bq,
       float* __restrict__ out)
{
    __shared__ float As[2][16][132];   // As[buf][k][m], padded
    __shared__ float Bs[2][16][132];   // Bs[buf][k][n], padded

    const int tid   = threadIdx.x;
    const int tx    = tid & 15;        // n microtile index
    const int ty    = tid >> 4;        // m microtile index
    const int mbase = blockIdx.y * 128;
    const int nbase = blockIdx.x * 128;
    const float* A  = g_Hs;

    const int aRow = tid >> 2;          // 0..63
    const int aCol = (tid & 3) * 4;     // 0,4,8,12
    const int bK   = tid >> 5;          // 0..7
    const int bN   = (tid & 31) * 4;    // 0..124

    float4 ra0, ra1, rb0, rb1;
    // prologue: stage chunk 0
    ra0 = *(const float4*)(A + (size_t)(mbase + aRow) * H_ + aCol);
    ra1 = *(const float4*)(A + (size_t)(mbase + aRow + 64) * H_ + aCol);
    rb0 = *(const float4*)(Bmat + (size_t)bK * V_ + nbase + bN);
    rb1 = *(const float4*)(Bmat + (size_t)(bK + 8) * V_ + nbase + bN);
    As[0][aCol + 0][aRow] = ra0.x; As[0][aCol + 1][aRow] = ra0.y;
    As[0][aCol + 2][aRow] = ra0.z; As[0][aCol + 3][aRow] = ra0.w;
    As[0][aCol + 0][aRow + 64] = ra1.x; As[0][aCol + 1][aRow + 64] = ra1.y;
    As[0][aCol + 2][aRow + 64] = ra1.z; As[0][aCol + 3][aRow + 64] = ra1.w;
    *(float4*)&Bs[0][bK][bN]     = rb0;
    *(float4*)&Bs[0][bK + 8][bN] = rb1;

    uint64_t c2[8][4];
#pragma unroll
    for (int i = 0; i < 8; i++)
#pragma unroll
        for (int j = 0; j < 4; j++) c2[i][j] = 0;

    for (int kc = 0; kc < 32; kc++) {
        const int cur = kc & 1;
        __syncthreads();
        if (kc < 31) {
            const int kn = (kc + 1) * 16;
            ra0 = *(const float4*)(A + (size_t)(mbase + aRow) * H_ + kn + aCol);
            ra1 = *(const float4*)(A + (size_t)(mbase + aRow + 64) * H_ + kn + aCol);
            rb0 = *(const float4*)(Bmat + (size_t)(kn + bK) * V_ + nbase + bN);
            rb1 = *(const float4*)(Bmat + (size_t)(kn + bK + 8) * V_ + nbase + bN);
        }
#pragma unroll
        for (int kk = 0; kk < 16; kk++) {
            float4 A0 = *(const float4*)&As[cur][kk][ty * 8];
            float4 A1 = *(const float4*)&As[cur][kk][ty * 8 + 4];
            const uint64_t* bp = (const uint64_t*)&Bs[cur][kk][tx * 8];
            uint64_t q0 = bp[0], q1 = bp[1], q2 = bp[2], q3 = bp[3];
            float a[8] = {A0.x, A0.y, A0.z, A0.w, A1.x, A1.y, A1.z, A1.w};
#pragma unroll
            for (int i = 0; i < 8; i++) {
                uint64_t ad = dup2(a[i]);
                fma2(c2[i][0], ad, q0); fma2(c2[i][1], ad, q1);
                fma2(c2[i][2], ad, q2); fma2(c2[i][3], ad, q3);
            }
        }
        if (kc < 31) {
            const int nxt = cur ^ 1;
            As[nxt][aCol + 0][aRow] = ra0.x; As[nxt][aCol + 1][aRow] = ra0.y;
            As[nxt][aCol + 2][aRow] = ra0.z; As[nxt][aCol + 3][aRow] = ra0.w;
            As[nxt][aCol + 0][aRow + 64] = ra1.x; As[nxt][aCol + 1][aRow + 64] = ra1.y;
            As[nxt][aCol + 2][aRow + 64] = ra1.z; As[nxt][aCol + 3][aRow + 64] = ra1.w;
            *(float4*)&Bs[nxt][bK][bN]     = rb0;
            *(float4*)&Bs[nxt][bK + 8][bN] = rb1;
        }
    }

    float4 q0 = *(const float4*)(bq + nbase + tx * 8);
    float4 q1 = *(const float4*)(bq + nbase + tx * 8 + 4);
#pragma unroll
    for (int i = 0; i < 8; i++) {
        float2 v0 = unpk(c2[i][0]), v1 = unpk(c2[i][1]);
        float2 v2 = unpk(c2[i][2]), v3 = unpk(c2[i][3]);
        float4 o0 = make_float4(v0.x + q0.x, v0.y + q0.y, v1.x + q0.z, v1.y + q0.w);
        float4 o1 = make_float4(v2.x + q1.x, v2.y + q1.y, v3.x + q1.z, v3.y + q1.w);
        size_t row = (size_t)(mbase + ty * 8 + i);
        *(float4*)(out + row * V_ + nbase + tx * 8)     = o0;
        *(float4*)(out + row * V_ + nbase + tx * 8 + 4) = o1;
    }
}

// Optional tail: H_final appended after the logits, if the harness expects it.
__global__ void k_hfinal(float* __restrict__ out)
{
    int i = blockIdx.x * blockDim.x + threadIdx.x;
    if (i < B_ * H_)
        out[YELEMS + i] = g_Hs[(size_t)(T_ - 1) * B_ * H_ + i];
}

extern "C" void kernel_launch(void* const* d_in, const int* in_sizes, int n_in,
                              void* d_out, int out_size)
{
    const int*   X   = (const int*)  d_in[0];
    const float* st  = (const float*)d_in[1];
    const float* Wxh = (const float*)d_in[2];
    const float* Whh = (const float*)d_in[3];
    const float* bh  = (const float*)d_in[4];
    const float* Whq = (const float*)d_in[5];
    const float* bq  = (const float*)d_in[6];
    float* out = (float*)d_out;

    k_rnn<<<128, 512>>>(X, st, Wxh, Whh, bh);

    dim3 g(V_ / 128, M_ / 128);   // (32, 128)
    k_gemm<<<g, 256>>>(Whq, bq, out);

    if ((long long)out_size >= YELEMS + (long long)(B_ * H_))
        k_hfinal<<<(B_ * H_ + 255) / 256, 256>>>(out);
}

// round 10
// speedup vs baseline: 1.4218x; 1.4218x over previous
#include <cuda_runtime.h>
#include <cuda_bf16.h>
#include <cstdint>

#define B_  32
#define T_  512
#define H_  512
#define V_  4096
#define M_  (B_ * T_)
#define YELEMS ((long long)M_ * V_)

__device__ float          g_Hs [M_ * H_];
__device__ __nv_bfloat16  g_Ahi[M_ * H_];
__device__ __nv_bfloat16  g_Alo[M_ * H_];
__device__ __nv_bfloat16  g_Bhi[V_ * H_];
__device__ __nv_bfloat16  g_Blo[V_ * H_];

__device__ __forceinline__ uint32_t smem_u32(const void* p) {
    uint32_t a;
    asm("{ .reg .u64 t; cvta.to.shared.u64 t, %1; cvt.u32.u64 %0, t; }" : "=r"(a) : "l"(p));
    return a;
}
__device__ __forceinline__ void cp16(uint32_t smem_addr, const void* g) {
    asm volatile("cp.async.cg.shared.global [%0], [%1], 16;"
                 :: "r"(smem_addr), "l"(g) : "memory");
}
#define CP_COMMIT() asm volatile("cp.async.commit_group;" ::: "memory")

__device__ __forceinline__ uint32_t swz(uint32_t o) { return o ^ ((o >> 3) & 0x70); }

// bf16 m16n8k16 MMA, fp32 accumulate (base sm_80+ feature — no 'a' target needed)
__device__ __forceinline__ void mma_bf16(float* d, const uint32_t* a, const uint32_t* b) {
    asm volatile(
        "mma.sync.aligned.m16n8k16.row.col.f32.bf16.bf16.f32 "
        "{%0,%1,%2,%3}, {%4,%5,%6,%7}, {%8,%9}, {%0,%1,%2,%3};"
        : "+f"(d[0]), "+f"(d[1]), "+f"(d[2]), "+f"(d[3])
        : "r"(a[0]), "r"(a[1]), "r"(a[2]), "r"(a[3]), "r"(b[0]), "r"(b[1]));
}
__device__ __forceinline__ void ldsm4(uint32_t* r, uint32_t addr) {
    asm volatile("ldmatrix.sync.aligned.m8n8.x4.shared.b16 {%0,%1,%2,%3}, [%4];"
                 : "=r"(r[0]), "=r"(r[1]), "=r"(r[2]), "=r"(r[3]) : "r"(addr));
}

__device__ __forceinline__ void fma2(uint64_t& d, uint64_t a, uint64_t b) {
    asm("fma.rn.f32x2 %0, %1, %2, %0;" : "+l"(d) : "l"(a), "l"(b));
}
__device__ __forceinline__ float2 unpk(uint64_t v) {
    float2 f; asm("mov.b64 {%0, %1}, %2;" : "=f"(f.x), "=f"(f.y) : "l"(v)); return f;
}

// ============================ recurrence ============================
// Epilogue also emits the bf16 hi/lo split of H directly (fused convA).
__global__ void __launch_bounds__(512, 1) __cluster_dims__(8, 1, 1)
k_rnn(const int* __restrict__ X, const float* __restrict__ state,
      const float* __restrict__ W_xh, const float* __restrict__ W_hh,
      const float* __restrict__ b_h)
{
    __shared__ double2 hsmD[512];
    __shared__ float4  part[512];

    const int tid = threadIdx.x;
    const int w   = tid >> 5;
    const int l   = tid & 31;
    const int bg  = blockIdx.x >> 3;
    const int cr  = blockIdx.x & 7;
    const int b0  = bg * 2;
    const int j0  = cr * 64;
    const int jj  = j0 + l * 2;
    const int k0  = w * 32;

    uint64_t wr[32];
#pragma unroll
    for (int kk = 0; kk < 32; kk++)
        wr[kk] = *(const uint64_t*)(W_hh + (size_t)(k0 + kk) * H_ + jj);

    for (int t = 0; t < T_; t++) {
        const float* s0 = (t == 0)
            ? (state + (size_t)b0 * H_)
            : (g_Hs + ((size_t)(t - 1) * B_ + b0) * H_);
        {
            float a = s0[tid];
            float b = s0[H_ + tid];
            ((float4*)hsmD)[tid] = make_float4(a, a, b, b);
        }
        __syncthreads();

        uint64_t acc0 = 0, acc1 = 0;
#pragma unroll
        for (int kk = 0; kk < 32; kk++) {
            double2 hd = hsmD[k0 + kk];
            fma2(acc0, __double_as_longlong(hd.x), wr[kk]);
            fma2(acc1, __double_as_longlong(hd.y), wr[kk]);
        }
        float2 a0 = unpk(acc0), a1 = unpk(acc1);
        part[w * 32 + l] = make_float4(a0.x, a0.y, a1.x, a1.y);
        __syncthreads();

        if (tid < 128) {
            int b  = tid >> 6;
            int jl = tid & 63;
            const float* pf = (const float*)part;
            int off = (jl >> 1) * 4 + b * 2 + (jl & 1);
            float s = 0.f;
#pragma unroll
            for (int ww = 0; ww < 16; ww++) s += pf[ww * 128 + off];
            int br  = b0 + b;
            int jgl = j0 + jl;
            int tok = X[br * T_ + t];
            float v = s + b_h[jgl] + W_xh[(size_t)tok * H_ + jgl];
            float h = tanhf(v);
            size_t idx = ((size_t)t * B_ + br) * H_ + jgl;
            g_Hs[idx] = h;
            __nv_bfloat16 hi = __float2bfloat16(h);
            g_Ahi[idx] = hi;
            g_Alo[idx] = __float2bfloat16(h - __bfloat162float(hi));
        }
        asm volatile("barrier.cluster.arrive.aligned;" ::: "memory");
        asm volatile("barrier.cluster.wait.aligned;" ::: "memory");
    }
}

// ============================ conversion (B only) ============================
__global__ void __launch_bounds__(256) k_convB(const float* __restrict__ W)
{
    __shared__ float tile[32][33];
    const int n0 = blockIdx.x * 32;
    const int k0 = blockIdx.y * 32;
    const int tx = threadIdx.x & 31;
    const int ty = threadIdx.x >> 5;
    for (int r = ty; r < 32; r += 8)
        tile[r][tx] = W[(size_t)(k0 + r) * V_ + n0 + tx];
    __syncthreads();
    for (int r = ty; r < 32; r += 8) {
        float v = tile[tx][r];
        __nv_bfloat16 h = __float2bfloat16(v);
        g_Bhi[(size_t)(n0 + r) * H_ + k0 + tx] = h;
        g_Blo[(size_t)(n0 + r) * H_ + k0 + tx] =
            __float2bfloat16(v - __bfloat162float(h));
    }
}

// ============================ mma.sync GEMM ============================
// C(16384x4096) = A @ Bt^T + bias, bf16 hi/lo 3-pass, fp32 accum in regs.
// CTA tile 128x128, 8 warps (4 x 2), warp tile 32x64. K-chunk 64, double buffer.
#define ST_AH 0u
#define ST_AL 16384u
#define ST_BH 32768u
#define ST_BL 49152u
#define ST_SZ 65536u
#define GEMM_DSMEM (1024u + 2u * ST_SZ)

__global__ void __launch_bounds__(256, 1)
k_gemm_mma(const float* __restrict__ bq, float* __restrict__ out)
{
    extern __shared__ char dsm[];
    __shared__ float s_bias[128];

    const uint32_t base = (smem_u32(dsm) + 1023u) & ~1023u;
    const int tid = threadIdx.x;
    const int wid = tid >> 5;
    const int lid = tid & 31;
    const int wm  = wid & 3;          // 4 warps along M (32 rows each)
    const int wn  = wid >> 2;         // 2 warps along N (64 cols each)
    const int m0  = blockIdx.y * 128;
    const int n0  = blockIdx.x * 128;

    if (tid < 128) s_bias[tid] = bq[n0 + tid];

    // ---- per-lane ldmatrix address components (swizzle decomposed) ----
    const int sub = lid >> 3;          // 0..3 (which 8x8 matrix)
    const int rr  = lid & 7;
    uint32_t arow[2], akb, axm[2];
    akb = (uint32_t)((sub >> 1) * 16);
#pragma unroll
    for (int mf = 0; mf < 2; mf++) {
        int row = wm * 32 + mf * 16 + (sub & 1) * 8 + rr;
        arow[mf] = (uint32_t)(row * 128);
        axm[mf]  = (uint32_t)((row & 7) * 16);
    }
    uint32_t brow[4], bkb, bxm[4];
    bkb = (uint32_t)((sub & 1) * 16);
#pragma unroll
    for (int p = 0; p < 4; p++) {
        int n = wn * 64 + p * 16 + (sub >> 1) * 8 + rr;
        brow[p] = (uint32_t)(n * 128);
        bxm[p]  = (uint32_t)((n & 7) * 16);
    }

    float acc[2][8][4];
#pragma unroll
    for (int mf = 0; mf < 2; mf++)
#pragma unroll
        for (int nf = 0; nf < 8; nf++)
#pragma unroll
            for (int q = 0; q < 4; q++) acc[mf][nf][q] = 0.f;

    auto load_chunk = [&](int kc, int buf) {
        const uint32_t sb = base + (uint32_t)buf * ST_SZ;
        const int kcol = kc * 64;
#pragma unroll
        for (int q = 0; q < 4; q++) {            // A: 128 rows x 8 16B units
            int u = tid + q * 256;
            int row = u >> 3, c = u & 7;
            uint32_t dst = swz((uint32_t)(row * 128 + c * 16));
            size_t gi = (size_t)(m0 + row) * H_ + kcol + c * 8;
            cp16(sb + ST_AH + dst, g_Ahi + gi);
            cp16(sb + ST_AL + dst, g_Alo + gi);
        }
#pragma unroll
        for (int q = 0; q < 4; q++) {            // B: 128 rows x 8 16B units
            int u = tid + q * 256;
            int row = u >> 3, c = u & 7;
            uint32_t dst = swz((uint32_t)(row * 128 + c * 16));
            size_t gi = (size_t)(n0 + row) * H_ + kcol + c * 8;
            cp16(sb + ST_BH + dst, g_Bhi + gi);
            cp16(sb + ST_BL + dst, g_Blo + gi);
        }
        CP_COMMIT();
    };

    load_chunk(0, 0);

    for (int c = 0; c < 8; c++) {
        if (c < 7) {
            load_chunk(c + 1, (c + 1) & 1);
            asm volatile("cp.async.wait_group 1;" ::: "memory");
        } else {
            asm volatile("cp.async.wait_group 0;" ::: "memory");
        }
        __syncthreads();

        const uint32_t sb = base + (uint32_t)(c & 1) * ST_SZ;
#pragma unroll
        for (int s = 0; s < 4; s++) {
            uint32_t ahi[2][4], alo[2][4];
#pragma unroll
            for (int mf = 0; mf < 2; mf++) {
                uint32_t off = arow[mf] + (((uint32_t)(s * 32) | akb) ^ axm[mf]);
                ldsm4(ahi[mf], sb + ST_AH + off);
                ldsm4(alo[mf], sb + ST_AL + off);
            }
            uint32_t bhi[4][4], blo[4][4];
#pragma unroll
            for (int p = 0; p < 4; p++) {
                uint32_t off = brow[p] + (((uint32_t)(s * 32) | bkb) ^ bxm[p]);
                ldsm4(bhi[p], sb + ST_BH + off);
                ldsm4(blo[p], sb + ST_BL + off);
            }
#pragma unroll
            for (int mf = 0; mf < 2; mf++)
#pragma unroll
                for (int p = 0; p < 4; p++) {
                    mma_bf16(acc[mf][2 * p],     ahi[mf], &bhi[p][0]);
                    mma_bf16(acc[mf][2 * p + 1], ahi[mf], &bhi[p][2]);
                    mma_bf16(acc[mf][2 * p],     ahi[mf], &blo[p][0]);
                    mma_bf16(acc[mf][2 * p + 1], ahi[mf], &blo[p][2]);
                    mma_bf16(acc[mf][2 * p],     alo[mf], &bhi[p][0]);
                    mma_bf16(acc[mf][2 * p + 1], alo[mf], &bhi[p][2]);
                }
        }
        __syncthreads();
    }

    // ---- epilogue: add bias, write fp32 ----
    const int lr = lid >> 2;          // 0..7
    const int lc = (lid & 3) * 2;     // 0,2,4,6
#pragma unroll
    for (int mf = 0; mf < 2; mf++) {
        int row0 = m0 + wm * 32 + mf * 16 + lr;
#pragma unroll
        for (int nf = 0; nf < 8; nf++) {
            int cl  = wn * 64 + nf * 8 + lc;
            float bx = s_bias[cl], by = s_bias[cl + 1];
            float2 v0 = make_float2(acc[mf][nf][0] + bx, acc[mf][nf][1] + by);
            float2 v1 = make_float2(acc[mf][nf][2] + bx, acc[mf][nf][3] + by);
            *(float2*)(out + (size_t)row0 * V_ + n0 + cl)       = v0;
            *(float2*)(out + (size_t)(row0 + 8) * V_ + n0 + cl) = v1;
        }
    }
}

__global__ void k_hfinal(float* __restrict__ out)
{
    int i = blockIdx.x * blockDim.x + threadIdx.x;
    if (i < B_ * H_)
        out[YELEMS + i] = g_Hs[(size_t)(T_ - 1) * B_ * H_ + i];
}

extern "C" void kernel_launch(void* const* d_in, const int* in_sizes, int n_in,
                              void* d_out, int out_size)
{
    const int*   X   = (const int*)  d_in[0];
    const float* st  = (const float*)d_in[1];
    const float* Wxh = (const float*)d_in[2];
    const float* Whh = (const float*)d_in[3];
    const float* bh  = (const float*)d_in[4];
    const float* Whq = (const float*)d_in[5];
    const float* bq  = (const float*)d_in[6];
    float* out = (float*)d_out;

    k_rnn<<<128, 512>>>(X, st, Wxh, Whh, bh);
    {
        dim3 gb(V_ / 32, H_ / 32);
        k_convB<<<gb, 256>>>(Whq);
    }
    cudaFuncSetAttribute(k_gemm_mma,
                         cudaFuncAttributeMaxDynamicSharedMemorySize,
                         GEMM_DSMEM);
    {
        dim3 g(V_ / 128, M_ / 128);   // (32, 128) -> 4096 CTAs
        k_gemm_mma<<<g, 256, GEMM_DSMEM>>>(bq, out);
    }
    if ((long long)out_size >= YELEMS + (long long)(B_ * H_))
        k_hfinal<<<(B_ * H_ + 255) / 256, 256>>>(out);
}